// round 4
// baseline (speedup 1.0000x reference)
#include <cuda_runtime.h>
#include <math.h>

#define EPSV 1e-5f

// ---------------- scratch (static device globals; no allocs) ----------------
__device__ float g_h1[4 * 64 * 64 * 128];    // conv1 out, NHWC
__device__ float g_h2[16384 * 256];          // conv2 out, NHWC
__device__ float g_s[4096 * 256];            // sequence [b*l, dm]
__device__ float g_xr[4096 * 1024];          // in_proj out (xi | silu(res))
__device__ float g_xlt[512 * 4096];          // depthwise conv out, TRANSPOSED [d][row]
__device__ float g_xdbl[4096 * 64];          // x_proj out (dt|B|C)
__device__ float g_deltat[512 * 4096];       // softplus(dt_proj), TRANSPOSED [d][row]
__device__ float g_rest[512 * 4096];         // silu(res), TRANSPOSED [d][row]
__device__ float g_yt[512 * 4096];           // scan out, TRANSPOSED [d][row]
__device__ float g_tmp[4096 * 256];          // out_proj out
__device__ float g_part[128 * 256];          // head partials
__device__ float g_v[4 * 256];               // pooled+LN features
__device__ float g_w2p[256 * 1152];          // permuted conv2 weights (tap-major)
__device__ float g_wpp[256 * 1024];          // permuted patchify weights (tap-major)

__device__ __forceinline__ float gelu_f(float v) {
    return 0.5f * v * (1.f + erff(v * 0.70710678118654752440f));
}
__device__ __forceinline__ float softplus_f(float x) {
    return fmaxf(x, 0.f) + log1pf(expf(-fabsf(x)));
}

// ---------------- packed f32x2 helpers (FFMA2 path, sm_103a) ----------------
__device__ __forceinline__ unsigned long long pk2(float lo, float hi) {
    unsigned long long r;
    asm("mov.b64 %0, {%1, %2};" : "=l"(r) : "f"(lo), "f"(hi));
    return r;
}
__device__ __forceinline__ void fma2(unsigned long long& d, unsigned long long a,
                                     unsigned long long b) {
    asm("fma.rn.f32x2 %0, %1, %2, %0;" : "+l"(d) : "l"(a), "l"(b));
}
__device__ __forceinline__ float2 upk2(unsigned long long v) {
    float2 f;
    asm("mov.b64 {%0, %1}, %2;" : "=f"(f.x), "=f"(f.y) : "l"(v));
    return f;
}

// ---------------- weight permutes (tap-major K so A gathers are contiguous) --
__global__ void permute_w2(const float* __restrict__ c2w) {
    int idx = blockIdx.x * 256 + threadIdx.x;
    if (idx >= 256 * 1152) return;
    int co = idx / 1152, k = idx % 1152;
    int r = k >> 7, ci = k & 127;
    g_w2p[idx] = c2w[co * 1152 + ci * 9 + r];
}
__global__ void permute_wp(const float* __restrict__ pw) {
    int idx = blockIdx.x * 256 + threadIdx.x;
    if (idx >= 256 * 1024) return;
    int co = idx >> 10, k = idx & 1023;
    int r = k >> 8, ci = k & 255;
    g_wpp[idx] = pw[(co << 10) + ci * 4 + r];
}

// ---------------- A-tile gather: 0=plain, 1=conv3x3 on g_h1, 2=patchify g_h2 -
template <int AMODE>
__device__ __forceinline__ float4 loadA(const float* __restrict__ A, int lda,
                                        int gr, int gk) {
    if (AMODE == 0) {
        return *(const float4*)(A + (size_t)gr * lda + gk);
    } else if (AMODE == 1) {
        int b = gr >> 12, yy = (gr >> 6) & 63, xx = gr & 63;
        int r = gk >> 7, ci = gk & 127;
        int ky = r / 3, kx = r - ky * 3;
        int iy = yy + ky - 1, ix = xx + kx - 1;
        if ((unsigned)iy < 64u && (unsigned)ix < 64u)
            return *(const float4*)&g_h1[(((b * 64 + iy) * 64 + ix) << 7) + ci];
        return make_float4(0.f, 0.f, 0.f, 0.f);
    } else {
        int b = gr >> 10, oy = (gr >> 5) & 31, ox = gr & 31;
        int r = gk >> 8, ci = gk & 255;
        int ky = r >> 1, kx = r & 1;
        return *(const float4*)&g_h2[(((b * 64 + 2 * oy + ky) * 64 + 2 * ox + kx) << 8) + ci];
    }
}

// ---------------- tiled double-buffered SGEMM (FFMA2): C = A * B^T ----------
// EPI: 0=none, 1=+bias[c], 2=bn+gelu, 3=softplus(+bias[c]), 4=+bias[c], silu c>=512,
//      5=softplus(+bias[r])   (row-bias, for transposed dt_proj)
template <int BM, int BN, int TM, int TN, int AMODE, int EPI>
__global__ void __launch_bounds__((BM / TM) * (BN / TN))
sgemm_nt(const float* __restrict__ A, int lda,
         const float* __restrict__ B, int ldb,
         float* __restrict__ C, int ldc,
         int K,
         const float* __restrict__ bias,
         const float* __restrict__ bn_g,
         const float* __restrict__ bn_b) {
    constexpr int BK = 8;
    constexpr int NT = (BM / TM) * (BN / TN);
    constexpr int AROWS = NT / 2;
    constexpr int NLA = BM / AROWS;
    constexpr int BROWS = NT / 2;
    constexpr int NLB = BN / BROWS;
    constexpr int TNH = TN / 2;

    __shared__ __align__(16) float As[2][BK][BM];
    __shared__ __align__(16) float Bs[2][BK][BN];

    const int tid = threadIdx.x;
    const int rowBase = blockIdx.y * BM;
    const int colBase = blockIdx.x * BN;
    const int tx = tid % (BN / TN);
    const int ty = tid / (BN / TN);
    const int lRow = tid >> 1;
    const int lCol = (tid & 1) * 4;

    const float* Bb = B + (size_t)(colBase + lRow) * ldb + lCol;

    unsigned long long acc2[TM][TNH];
#pragma unroll
    for (int i = 0; i < TM; i++)
#pragma unroll
        for (int j = 0; j < TNH; j++) acc2[i][j] = 0ull;

    float4 pa[NLA], pb[NLB];
#pragma unroll
    for (int p = 0; p < NLA; p++)
        pa[p] = loadA<AMODE>(A, lda, rowBase + lRow + p * AROWS, lCol);
#pragma unroll
    for (int p = 0; p < NLB; p++)
        pb[p] = *(const float4*)(Bb + (size_t)p * BROWS * ldb);
#pragma unroll
    for (int p = 0; p < NLA; p++) {
        As[0][lCol + 0][lRow + p * AROWS] = pa[p].x;
        As[0][lCol + 1][lRow + p * AROWS] = pa[p].y;
        As[0][lCol + 2][lRow + p * AROWS] = pa[p].z;
        As[0][lCol + 3][lRow + p * AROWS] = pa[p].w;
    }
#pragma unroll
    for (int p = 0; p < NLB; p++) {
        Bs[0][lCol + 0][lRow + p * BROWS] = pb[p].x;
        Bs[0][lCol + 1][lRow + p * BROWS] = pb[p].y;
        Bs[0][lCol + 2][lRow + p * BROWS] = pb[p].z;
        Bs[0][lCol + 3][lRow + p * BROWS] = pb[p].w;
    }
    __syncthreads();

    int buf = 0;
    for (int k0 = 0; k0 < K; k0 += BK) {
        const bool more = (k0 + BK) < K;
        if (more) {
#pragma unroll
            for (int p = 0; p < NLA; p++)
                pa[p] = loadA<AMODE>(A, lda, rowBase + lRow + p * AROWS, k0 + BK + lCol);
#pragma unroll
            for (int p = 0; p < NLB; p++)
                pb[p] = *(const float4*)(Bb + (size_t)p * BROWS * ldb + k0 + BK);
        }
#pragma unroll
        for (int kk = 0; kk < BK; kk++) {
            float ar[TM];
#pragma unroll
            for (int i = 0; i < TM; i += 4)
                *(float4*)&ar[i] = *(const float4*)&As[buf][kk][ty * TM + i];
            unsigned long long b2[TNH];
#pragma unroll
            for (int q = 0; q < TN / 4; q++) {
                ulonglong2 bv = *(const ulonglong2*)&Bs[buf][kk][tx * TN + 4 * q];
                b2[2 * q] = bv.x;
                b2[2 * q + 1] = bv.y;
            }
#pragma unroll
            for (int i = 0; i < TM; i++) {
                unsigned long long a2 = pk2(ar[i], ar[i]);
#pragma unroll
                for (int j = 0; j < TNH; j++) fma2(acc2[i][j], a2, b2[j]);
            }
        }
        if (more) {
#pragma unroll
            for (int p = 0; p < NLA; p++) {
                As[buf ^ 1][lCol + 0][lRow + p * AROWS] = pa[p].x;
                As[buf ^ 1][lCol + 1][lRow + p * AROWS] = pa[p].y;
                As[buf ^ 1][lCol + 2][lRow + p * AROWS] = pa[p].z;
                As[buf ^ 1][lCol + 3][lRow + p * AROWS] = pa[p].w;
            }
#pragma unroll
            for (int p = 0; p < NLB; p++) {
                Bs[buf ^ 1][lCol + 0][lRow + p * BROWS] = pb[p].x;
                Bs[buf ^ 1][lCol + 1][lRow + p * BROWS] = pb[p].y;
                Bs[buf ^ 1][lCol + 2][lRow + p * BROWS] = pb[p].z;
                Bs[buf ^ 1][lCol + 3][lRow + p * BROWS] = pb[p].w;
            }
            __syncthreads();
            buf ^= 1;
        }
    }

#pragma unroll
    for (int i = 0; i < TM; i++) {
        const int r = rowBase + ty * TM + i;
        float* crow = C + (size_t)r * ldc + colBase + tx * TN;
        float vv[TN];
#pragma unroll
        for (int j = 0; j < TNH; j++) {
            float2 f = upk2(acc2[i][j]);
            vv[2 * j] = f.x;
            vv[2 * j + 1] = f.y;
        }
#pragma unroll
        for (int j = 0; j < TN; j++) {
            const int c = colBase + tx * TN + j;
            float v = vv[j];
            if (EPI == 1) v += bias[c];
            else if (EPI == 2) {
                v += bias[c];
                v = v * (bn_g[c] * rsqrtf(1.f + EPSV)) + bn_b[c];
                v = gelu_f(v);
            } else if (EPI == 3) {
                v = softplus_f(v + bias[c]);
            } else if (EPI == 4) {
                v += bias[c];
                if (c >= 512) v = v * __frcp_rn(1.f + __expf(-v));
            } else if (EPI == 5) {
                v = softplus_f(v + bias[r]);
            }
            vv[j] = v;
        }
#pragma unroll
        for (int j4 = 0; j4 < TN; j4 += 4)
            *(float4*)&crow[j4] = make_float4(vv[j4], vv[j4 + 1], vv[j4 + 2], vv[j4 + 3]);
    }
}

// ---------------- TN SGEMM (A stored K-major, FFMA2): C[M,N] = At^T * B^T ----
template <int EPI>
__global__ void __launch_bounds__(128)
sgemm_tn64(const float* __restrict__ At, int Mtot,
           const float* __restrict__ B, int ldb,
           float* __restrict__ C, int ldc, int K,
           const float* __restrict__ bias) {
    __shared__ __align__(16) float As[2][8][64];
    __shared__ __align__(16) float Bs[2][8][64];
    const int tid = threadIdx.x;
    const int rowBase = blockIdx.y * 64;
    const int colBase = blockIdx.x * 64;
    const int tx = tid & 7, ty = tid >> 3;
    const int akr = tid >> 4, amc = (tid & 15) * 4;
    const int lRow = tid >> 1, lCol = (tid & 1) * 4;

    const float* Abase = At + (size_t)akr * Mtot + rowBase + amc;
    const float* Bb = B + (size_t)(colBase + lRow) * ldb + lCol;

    unsigned long long acc2[4][4];
#pragma unroll
    for (int i = 0; i < 4; i++)
#pragma unroll
        for (int j = 0; j < 4; j++) acc2[i][j] = 0ull;

    float4 pa = *(const float4*)Abase;
    float4 pb = *(const float4*)Bb;
    *(float4*)&As[0][akr][amc] = pa;
    Bs[0][lCol + 0][lRow] = pb.x;
    Bs[0][lCol + 1][lRow] = pb.y;
    Bs[0][lCol + 2][lRow] = pb.z;
    Bs[0][lCol + 3][lRow] = pb.w;
    __syncthreads();

    int buf = 0;
    for (int k0 = 0; k0 < K; k0 += 8) {
        const bool more = (k0 + 8) < K;
        if (more) {
            pa = *(const float4*)(Abase + (size_t)(k0 + 8) * Mtot);
            pb = *(const float4*)(Bb + k0 + 8);
        }
#pragma unroll
        for (int kk = 0; kk < 8; kk++) {
            float ar[4];
            *(float4*)&ar[0] = *(const float4*)&As[buf][kk][ty * 4];
            unsigned long long b2[4];
            ulonglong2 bv0 = *(const ulonglong2*)&Bs[buf][kk][tx * 8];
            ulonglong2 bv1 = *(const ulonglong2*)&Bs[buf][kk][tx * 8 + 4];
            b2[0] = bv0.x; b2[1] = bv0.y; b2[2] = bv1.x; b2[3] = bv1.y;
#pragma unroll
            for (int i = 0; i < 4; i++) {
                unsigned long long a2 = pk2(ar[i], ar[i]);
#pragma unroll
                for (int j = 0; j < 4; j++) fma2(acc2[i][j], a2, b2[j]);
            }
        }
        if (more) {
            *(float4*)&As[buf ^ 1][akr][amc] = pa;
            Bs[buf ^ 1][lCol + 0][lRow] = pb.x;
            Bs[buf ^ 1][lCol + 1][lRow] = pb.y;
            Bs[buf ^ 1][lCol + 2][lRow] = pb.z;
            Bs[buf ^ 1][lCol + 3][lRow] = pb.w;
            __syncthreads();
            buf ^= 1;
        }
    }

#pragma unroll
    for (int i = 0; i < 4; i++) {
        const int r = rowBase + ty * 4 + i;
        float* crow = C + (size_t)r * ldc + colBase + tx * 8;
        float vv[8];
#pragma unroll
        for (int j = 0; j < 4; j++) {
            float2 f = upk2(acc2[i][j]);
            vv[2 * j] = f.x;
            vv[2 * j + 1] = f.y;
        }
#pragma unroll
        for (int j = 0; j < 8; j++) {
            const int c = colBase + tx * 8 + j;
            if (EPI == 1) vv[j] += bias[c];
        }
        *(float4*)&crow[0] = make_float4(vv[0], vv[1], vv[2], vv[3]);
        *(float4*)&crow[4] = make_float4(vv[4], vv[5], vv[6], vv[7]);
    }
}

// ---------------- conv stem ----------------
__global__ void conv1_kernel(const float* __restrict__ x, const float* __restrict__ w,
                             const float* __restrict__ bias, const float* __restrict__ g,
                             const float* __restrict__ bb) {
    int idx = blockIdx.x * 256 + threadIdx.x;
    if (idx >= 4 * 64 * 64 * 128) return;
    int co = idx & 127;
    int xx = (idx >> 7) & 63;
    int yy = (idx >> 13) & 63;
    int b = idx >> 19;
    float acc = bias[co];
#pragma unroll
    for (int ci = 0; ci < 3; ci++)
#pragma unroll
        for (int ky = 0; ky < 3; ky++) {
            int iy = yy + ky - 1;
            if ((unsigned)iy >= 64u) continue;
#pragma unroll
            for (int kx = 0; kx < 3; kx++) {
                int ix = xx + kx - 1;
                if ((unsigned)ix >= 64u) continue;
                acc += x[((b * 3 + ci) * 64 + iy) * 64 + ix] * w[((co * 3 + ci) * 3 + ky) * 3 + kx];
            }
        }
    float v = acc * (g[co] * rsqrtf(1.f + EPSV)) + bb[co];
    g_h1[idx] = gelu_f(v);
}

// ---------------- mamba pieces ----------------
// depthwise conv with transposed output: g_xlt[d][row]; 64 rows x 64 d tile
__global__ void __launch_bounds__(256) dwconv_t_kernel(const float* __restrict__ cw,
                                                       const float* __restrict__ cb) {
    __shared__ float sin[67][64];
    __shared__ float sout[64][65];
    const int r0g = blockIdx.x * 64;
    const int d0 = blockIdx.y * 64;
    const int tid = threadIdx.x;
    const int b = r0g >> 10;
    const int l0 = r0g & 1023;

    for (int idx = tid; idx < 67 * 64; idx += 256) {
        int rr = idx >> 6;
        int dc = idx & 63;
        int l = l0 + rr - 1;
        float v = 0.f;
        if ((unsigned)l < 1024u)
            v = g_xr[((size_t)(b * 1024 + l) << 10) + d0 + dc];
        sin[rr][dc] = v;
    }
    __syncthreads();

    const int dc = tid & 63;
    const int rbase = (tid >> 6) * 16;
    const float4 w = *(const float4*)&cw[(d0 + dc) * 4];
    const float bi = cb[d0 + dc];
#pragma unroll
    for (int o = 0; o < 16; o++) {
        int r = rbase + o;
        float acc = bi;
        acc = fmaf(sin[r + 0][dc], w.x, acc);
        acc = fmaf(sin[r + 1][dc], w.y, acc);
        acc = fmaf(sin[r + 2][dc], w.z, acc);
        acc = fmaf(sin[r + 3][dc], w.w, acc);
        sout[dc][r] = acc;
    }
    __syncthreads();

    for (int idx = tid; idx < 4096; idx += 256) {
        int dr = idx >> 6, rc = idx & 63;
        g_xlt[(size_t)(d0 + dr) * 4096 + r0g + rc] = sout[dr][rc];
    }
}

// transpose silu(res) half of g_xr: g_rest[d][row]
__global__ void __launch_bounds__(256) transpose_res_kernel() {
    __shared__ float tile[32][33];
    const int r0 = blockIdx.x * 32;
    const int d0 = blockIdx.y * 32;
    const int tx = threadIdx.x & 31, ty = threadIdx.x >> 5;
#pragma unroll
    for (int o = 0; o < 32; o += 8)
        tile[ty + o][tx] = g_xr[((size_t)(r0 + ty + o) << 10) + 512 + d0 + tx];
    __syncthreads();
#pragma unroll
    for (int o = 0; o < 32; o += 8)
        g_rest[(size_t)(d0 + ty + o) * 4096 + r0 + tx] = tile[tx][ty + o];
}

// Chunked scan: 1 block per (b,d). 16 chunks x 64 steps. 256 thr = 16 chunks x 16 states.
// All big operands read from transposed [d][row] buffers (contiguous).
__global__ void __launch_bounds__(256)
scan_kernel(const float* __restrict__ alog_l, const float* __restrict__ dssm_l) {
    const int d = blockIdx.x & 511;
    const int b = blockIdx.x >> 9;
    const int t = threadIdx.x;
    const int n = t & 15;
    const int c = t >> 4;

    __shared__ float sh_hend[16][16];
    __shared__ float sh_S[16];
    __shared__ float sh_y[1024];

    const float Adn = -__expf(alog_l[d * 16 + n]);
    const float Dd = dssm_l[d];

    const size_t base = (size_t)d * 4096 + (size_t)b * 1024 + c * 64;
    const float* pDelta = g_deltat + base;
    const float* pU     = g_xlt + base;
    const float* pRes   = g_rest + base;
    const int rb = b * 1024 + c * 64;
    const float* pB = g_xdbl + ((size_t)rb << 6) + 32 + n;
    const float* pC = g_xdbl + ((size_t)rb << 6) + 48 + n;

    // pass 1: chunk-local end state + delta sum
    float h = 0.f, S = 0.f;
#pragma unroll 4
    for (int j = 0; j < 64; j++) {
        float dl = pDelta[j];
        float u  = pU[j];
        float Bv = pB[j << 6];
        float a = __expf(dl * Adn);
        h = fmaf(a, h, dl * Bv * u);
        S += dl;
    }
    sh_hend[c][n] = h;
    if (n == 0) sh_S[c] = S;
    __syncthreads();

    // carry-in
    float H0 = 0.f, Q = 0.f;
    for (int cp = c - 1; cp >= 0; cp--) {
        H0 = fmaf(sh_hend[cp][n], __expf(Adn * Q), H0);
        Q += sh_S[cp];
    }

    // pass 2: apply with carry, reduce over n, stage y in smem
    h = H0;
#pragma unroll 2
    for (int j = 0; j < 64; j++) {
        float dl = pDelta[j];
        float u  = pU[j];
        float Bv = pB[j << 6];
        float Cv = pC[j << 6];
        float a = __expf(dl * Adn);
        h = fmaf(a, h, dl * Bv * u);
        float p = h * Cv;
        p += __shfl_xor_sync(0xFFFFFFFFu, p, 1);
        p += __shfl_xor_sync(0xFFFFFFFFu, p, 2);
        p += __shfl_xor_sync(0xFFFFFFFFu, p, 4);
        p += __shfl_xor_sync(0xFFFFFFFFu, p, 8);
        if (n == 0) {
            float sres = pRes[j];
            sh_y[c * 64 + j] = (p + u * Dd) * sres;
        }
    }
    __syncthreads();

    *(float4*)&g_yt[(size_t)d * 4096 + (size_t)b * 1024 + t * 4] = *(float4*)&sh_y[t * 4];
}

__global__ void ln_add_kernel(const float* __restrict__ w, const float* __restrict__ bi) {
    int row = blockIdx.x;
    int t = threadIdx.x;
    __shared__ float sh[256];
    float v = g_tmp[(size_t)row * 256 + t];
    sh[t] = v;
    __syncthreads();
    for (int o = 128; o > 0; o >>= 1) { if (t < o) sh[t] += sh[t + o]; __syncthreads(); }
    float mean = sh[0] * (1.f / 256.f);
    __syncthreads();
    float dv = v - mean;
    sh[t] = dv * dv;
    __syncthreads();
    for (int o = 128; o > 0; o >>= 1) { if (t < o) sh[t] += sh[t + o]; __syncthreads(); }
    float var = sh[0] * (1.f / 256.f);
    g_s[(size_t)row * 256 + t] += dv * rsqrtf(var + EPSV) * w[t] + bi[t];
}

// ---------------- head ----------------
__global__ void head1_kernel() {
    int b = blockIdx.x >> 5, ch = blockIdx.x & 31, t = threadIdx.x;
    float acc = 0.f;
    const float* p = g_s + (size_t)((b << 10) + ch * 32) * 256 + t;
#pragma unroll 8
    for (int l = 0; l < 32; l++) acc += p[(size_t)l * 256];
    g_part[blockIdx.x * 256 + t] = acc;
}

__global__ void head2_kernel(const float* __restrict__ nw, const float* __restrict__ nb) {
    int b = blockIdx.x, t = threadIdx.x;
    float acc = 0.f;
#pragma unroll
    for (int c = 0; c < 32; c++) acc += g_part[((b << 5) + c) * 256 + t];
    float m = acc * (1.f / 1024.f);
    __shared__ float sh[256];
    sh[t] = m;
    __syncthreads();
    for (int o = 128; o > 0; o >>= 1) { if (t < o) sh[t] += sh[t + o]; __syncthreads(); }
    float mu = sh[0] * (1.f / 256.f);
    __syncthreads();
    float dv = m - mu;
    sh[t] = dv * dv;
    __syncthreads();
    for (int o = 128; o > 0; o >>= 1) { if (t < o) sh[t] += sh[t + o]; __syncthreads(); }
    float var = sh[0] * (1.f / 256.f);
    g_v[b * 256 + t] = dv * rsqrtf(var + EPSV) * nw[t] + nb[t];
}

__global__ void fc_kernel(const float* __restrict__ fcw, const float* __restrict__ fcb,
                          float* __restrict__ out) {
    int idx = blockIdx.x * 256 + threadIdx.x;
    if (idx >= 4000) return;
    int b = idx / 1000, n = idx % 1000;
    float acc = fcb[n];
    const float* v = g_v + b * 256;
    const float* w = fcw + n * 256;
#pragma unroll 8
    for (int k = 0; k < 256; k++) acc += v[k] * w[k];
    out[idx] = acc;
}

__global__ void softmax_kernel(float* __restrict__ out) {
    int b = blockIdx.x, t = threadIdx.x;
    __shared__ float sh[256];
    const float* lg = out + b * 1000;
    float mx = -1e30f;
    for (int i = t; i < 1000; i += 256) mx = fmaxf(mx, lg[i]);
    sh[t] = mx;
    __syncthreads();
    for (int o = 128; o > 0; o >>= 1) { if (t < o) sh[t] = fmaxf(sh[t], sh[t + o]); __syncthreads(); }
    mx = sh[0];
    __syncthreads();
    float s = 0.f;
    for (int i = t; i < 1000; i += 256) s += expf(lg[i] - mx);
    sh[t] = s;
    __syncthreads();
    for (int o = 128; o > 0; o >>= 1) { if (t < o) sh[t] += sh[t + o]; __syncthreads(); }
    float inv = 1.f / sh[0];
    for (int i = t; i < 1000; i += 256) out[4000 + b * 1000 + i] = expf(lg[i] - mx) * inv;
}

// ---------------- launch ----------------
extern "C" void kernel_launch(void* const* d_in, const int* in_sizes, int n_in,
                              void* d_out, int out_size) {
    const float* x    = (const float*)d_in[0];
    const float* c1w  = (const float*)d_in[1];
    const float* c1b  = (const float*)d_in[2];
    const float* g1   = (const float*)d_in[3];
    const float* b1   = (const float*)d_in[4];
    const float* c2w  = (const float*)d_in[5];
    const float* c2b  = (const float*)d_in[6];
    const float* g2   = (const float*)d_in[7];
    const float* b2   = (const float*)d_in[8];
    const float* pw   = (const float*)d_in[9];
    const float* pb   = (const float*)d_in[10];
    const float* g3   = (const float*)d_in[11];
    const float* b3   = (const float*)d_in[12];
    const float* ipw  = (const float*)d_in[13];
    const float* ipb  = (const float*)d_in[14];
    const float* cw   = (const float*)d_in[15];
    const float* cb   = (const float*)d_in[16];
    const float* xpw  = (const float*)d_in[17];
    const float* dpw  = (const float*)d_in[18];
    const float* dpb  = (const float*)d_in[19];
    const float* alog = (const float*)d_in[20];
    const float* dssm = (const float*)d_in[21];
    const float* opw  = (const float*)d_in[22];
    const float* opb  = (const float*)d_in[23];
    const float* lnw  = (const float*)d_in[24];
    const float* lnb  = (const float*)d_in[25];
    const float* nw   = (const float*)d_in[26];
    const float* nb   = (const float*)d_in[27];
    const float* fcw  = (const float*)d_in[28];
    const float* fcb  = (const float*)d_in[29];

    float *p_s, *p_xr, *p_xlt, *p_xdbl, *p_deltat, *p_yt, *p_tmp, *p_h2, *p_w2p, *p_wpp;
    cudaGetSymbolAddress((void**)&p_s, g_s);
    cudaGetSymbolAddress((void**)&p_xr, g_xr);
    cudaGetSymbolAddress((void**)&p_xlt, g_xlt);
    cudaGetSymbolAddress((void**)&p_xdbl, g_xdbl);
    cudaGetSymbolAddress((void**)&p_deltat, g_deltat);
    cudaGetSymbolAddress((void**)&p_yt, g_yt);
    cudaGetSymbolAddress((void**)&p_tmp, g_tmp);
    cudaGetSymbolAddress((void**)&p_h2, g_h2);
    cudaGetSymbolAddress((void**)&p_w2p, g_w2p);
    cudaGetSymbolAddress((void**)&p_wpp, g_wpp);

    // ---- stem ----
    permute_w2<<<(256 * 1152 + 255) / 256, 256>>>(c2w);
    permute_wp<<<(256 * 1024 + 255) / 256, 256>>>(pw);
    conv1_kernel<<<8192, 256>>>(x, c1w, c1b, g1, b1);
    // conv2 (implicit im2col): M=16384, N=256, K=1152
    sgemm_nt<128, 128, 8, 8, 1, 2><<<dim3(2, 128), 256>>>(nullptr, 0, p_w2p, 1152, p_h2, 256,
                                                          1152, c2b, g2, b2);
    // patchify (implicit): M=4096, N=256, K=1024
    sgemm_nt<64, 64, 4, 8, 2, 2><<<dim3(4, 64), 128>>>(nullptr, 0, p_wpp, 1024, p_s, 256,
                                                       1024, pb, g3, b3);

    // ---- mamba layers ----
    for (int i = 0; i < 4; i++) {
        const float* ipw_l  = ipw + (size_t)i * 1024 * 256;
        const float* ipb_l  = ipb + (size_t)i * 1024;
        const float* cw_l   = cw + (size_t)i * 512 * 4;
        const float* cb_l   = cb + (size_t)i * 512;
        const float* xpw_l  = xpw + (size_t)i * 64 * 512;
        const float* dpw_l  = dpw + (size_t)i * 512 * 32;
        const float* dpb_l  = dpb + (size_t)i * 512;
        const float* alog_l = alog + (size_t)i * 512 * 16;
        const float* dssm_l = dssm + (size_t)i * 512;
        const float* opw_l  = opw + (size_t)i * 256 * 512;
        const float* opb_l  = opb + (size_t)i * 256;
        const float* lnw_l  = lnw + (size_t)i * 256;
        const float* lnb_l  = lnb + (size_t)i * 256;

        // in_proj: M=4096, N=1024, K=256; silu applied to res half (cols>=512)
        sgemm_nt<128, 128, 8, 8, 0, 4><<<dim3(8, 32), 256>>>(p_s, 256, ipw_l, 256, p_xr, 1024,
                                                             256, ipb_l, nullptr, nullptr);
        transpose_res_kernel<<<dim3(128, 16), 256>>>();
        dwconv_t_kernel<<<dim3(64, 8), 256>>>(cw_l, cb_l);
        // x_proj (TN): At = g_xlt [512][4096], B = xpw [64][512] -> xdbl [4096][64]
        sgemm_tn64<0><<<dim3(1, 64), 128>>>(p_xlt, 4096, xpw_l, 512, p_xdbl, 64,
                                            512, nullptr);
        // dt_proj TRANSPOSED: M=512 (d), N=4096 (rows), K=32
        // A = dpw [512][32], B = g_xdbl rows (dt cols 0..31, ldb=64) -> g_deltat [512][4096]
        sgemm_nt<64, 128, 8, 8, 0, 5><<<dim3(32, 8), 128>>>(dpw_l, 32, p_xdbl, 64,
                                                            p_deltat, 4096, 32, dpb_l,
                                                            nullptr, nullptr);
        scan_kernel<<<2048, 256>>>(alog_l, dssm_l);
        // out_proj (TN): At = g_yt [512][4096], B = opw [256][512]
        sgemm_tn64<1><<<dim3(4, 64), 128>>>(p_yt, 4096, opw_l, 512, p_tmp, 256,
                                            512, opb_l);
        ln_add_kernel<<<4096, 256>>>(lnw_l, lnb_l);
    }

    // ---- head ----
    head1_kernel<<<128, 256>>>();
    head2_kernel<<<4, 256>>>(nw, nb);
    fc_kernel<<<16, 256>>>(fcw, fcb, (float*)d_out);
    if (out_size >= 8000) softmax_kernel<<<4, 256>>>((float*)d_out);
}